// round 13
// baseline (speedup 1.0000x reference)
#include <cuda_runtime.h>
#include <cstdint>
#include <cstddef>

#define T_STEPS 2048
#define BATCH   64
#define NIN     128
#define NHID    512
#define NOUT    64

#define THREADS 128          // each thread owns 4 adjacent j-columns

// h_all fallback if the harness output holds logits only
__device__ float g_hall[(size_t)T_STEPS * BATCH * NHID];

// ---- XLA llvm_ir::EmitFastTanh, with_fma = true ----
// Clamp to +/-7.99881172180175781; Cephes 7/4 rational, FUSED Horner steps
// (NVPTX/LLVM contract by default); single IEEE divide; |x| < 0.0004 (on
// ORIGINAL x) -> x.
__device__ __forceinline__ float tanh_xla(float x) {
    const float kClamp = 7.99881172180175781f;
    float xc = fminf(fmaxf(x, -kClamp), kClamp);
    float x2 = __fmul_rn(xc, xc);
    float p = -2.76076847742355e-16f;                 // alpha_13
    p = fmaf(x2, p,  2.00018790482477e-13f);          // alpha_11
    p = fmaf(x2, p, -8.60467152213735e-11f);          // alpha_9
    p = fmaf(x2, p,  5.12229709037114e-08f);          // alpha_7
    p = fmaf(x2, p,  1.48572235717979e-05f);          // alpha_5
    p = fmaf(x2, p,  6.37261928875436e-04f);          // alpha_3
    p = fmaf(x2, p,  4.89352455891786e-03f);          // alpha_1
    p = __fmul_rn(xc, p);
    float q = 1.19825839466702e-06f;                  // beta_6
    q = fmaf(x2, q,  1.18534705686654e-04f);          // beta_4
    q = fmaf(x2, q,  2.26843463243900e-03f);          // beta_2
    q = fmaf(x2, q,  4.89352518554385e-03f);          // beta_0
    float r = __fdiv_rn(p, q);
    return (fabsf(x) < 0.0004f) ? x : r;
}

// ---------------- Kernel 1: protocol-free recurrent scan ----------------
// 64 CTAs, one batch row each; full hidden state CTA-local (double-buffered
// SMEM); no inter-CTA communication. Thread tid owns columns j = 4t..4t+3.
// Reference-order arithmetic per output column j (cublas-SIMT / naive-LLVM
// dot: ONE serial fma chain, k ascending, accumulator from 0):
//   dot_h = sum_{k=0..511 asc} fmaf(h[k],  W_hh[k][j], .)
//   dot_u = sum_{i=0..127 asc} fmaf(u[i],  W_uh[i][j], .)
//   h' = tanh_xla( fadd(dot_h, fadd(dot_u, b_hh[j])) )
__global__ void __launch_bounds__(THREADS, 1)
scan_kernel(const float* __restrict__ u,
            const float* __restrict__ W_uh,
            const float* __restrict__ W_hh,
            const float* __restrict__ b_hh,
            float* __restrict__ h_all) {
    __shared__ float hbuf[2][NHID];      // double-buffered hidden state (this row)
    __shared__ float ubuf[2][NIN];       // double-buffered u_t (this row)

    const int tid = threadIdx.x;
    const int row = blockIdx.x;          // batch row
    const int j4  = tid * 4;             // first of this thread's 4 columns

    // init: h0 = 0; stage u_0
    hbuf[0][j4 + 0] = 0.f;
    hbuf[0][j4 + 1] = 0.f;
    hbuf[0][j4 + 2] = 0.f;
    hbuf[0][j4 + 3] = 0.f;
    if (tid < NIN / 4) {
        float4 v = *(const float4*)(u + (size_t)row * NIN + tid * 4);
        *(float4*)&ubuf[0][tid * 4] = v;
    }
    __syncthreads();

    const float4 bh4 = *(const float4*)(b_hh + j4);

    for (int t = 0; t < T_STEPS; t++) {
        const int cur = t & 1;
        const int nxt = cur ^ 1;

        // ---- dot_h: single serial chain, k = 0..511 ascending, from 0 ----
        float a0 = 0.f, a1 = 0.f, a2 = 0.f, a3 = 0.f;
        {
            const float* wp = W_hh + j4;
            const float* hp = hbuf[cur];
#pragma unroll 8
            for (int k = 0; k < NHID; k++) {
                float  hk = hp[k];                     // LDS broadcast
                float4 w  = *(const float4*)(wp + (size_t)k * NHID);
                a0 = fmaf(hk, w.x, a0);
                a1 = fmaf(hk, w.y, a1);
                a2 = fmaf(hk, w.z, a2);
                a3 = fmaf(hk, w.w, a3);
            }
        }

        // ---- dot_u: single serial chain, i = 0..127 ascending, from 0 ----
        float u0 = 0.f, u1 = 0.f, u2 = 0.f, u3 = 0.f;
        {
            const float* wp = W_uh + j4;
            const float* up = ubuf[cur];
#pragma unroll 8
            for (int i = 0; i < NIN; i++) {
                float  ui = up[i];                     // LDS broadcast
                float4 w  = *(const float4*)(wp + (size_t)i * NHID);
                u0 = fmaf(ui, w.x, u0);
                u1 = fmaf(ui, w.y, u1);
                u2 = fmaf(ui, w.z, u2);
                u3 = fmaf(ui, w.w, u3);
            }
        }

        // ---- reference combine: tanh( dot_h + (dot_u + bias) ) ----
        float4 val;
        val.x = tanh_xla(__fadd_rn(a0, __fadd_rn(u0, bh4.x)));
        val.y = tanh_xla(__fadd_rn(a1, __fadd_rn(u1, bh4.y)));
        val.z = tanh_xla(__fadd_rn(a2, __fadd_rn(u2, bh4.z)));
        val.w = tanh_xla(__fadd_rn(a3, __fadd_rn(u3, bh4.w)));

        // stream h_{t+1} to output tensor
        *(float4*)(h_all + (size_t)t * (BATCH * NHID) + (size_t)row * NHID + j4) = val;

        // write next hidden state (other parity)
        *(float4*)&hbuf[nxt][j4] = val;

        // stage u_{t+1} into the other parity
        if (t + 1 < T_STEPS && tid < NIN / 4) {
            float4 v = *(const float4*)(u + ((size_t)(t + 1) * BATCH + row) * NIN + tid * 4);
            *(float4*)&ubuf[nxt][tid * 4] = v;
        }

        __syncthreads();   // publish hbuf[nxt] / ubuf[nxt]
    }
}

// ---------------- Kernel 2: logits = h_last @ W_hy + b_hy ----------------
// Single serial chain, k ascending; bias added AFTER the dot.
__global__ __launch_bounds__(64) void logits_kernel(const float* __restrict__ h_last,
                                                    const float* __restrict__ W_hy,
                                                    const float* __restrict__ b_hy,
                                                    float* __restrict__ out) {
    __shared__ float hrow[NHID];
    const int bi = blockIdx.x;
    for (int k = threadIdx.x; k < NHID; k += blockDim.x)
        hrow[k] = h_last[(size_t)bi * NHID + k];
    __syncthreads();
    const int o = threadIdx.x;
    float acc = 0.f;
    for (int k = 0; k < NHID; k++)
        acc = fmaf(hrow[k], W_hy[(size_t)k * NOUT + o], acc);
    out[(size_t)bi * NOUT + o] = __fadd_rn(acc, b_hy[o]);
}

// ---------------- launch ----------------
extern "C" void kernel_launch(void* const* d_in, const int* in_sizes, int n_in,
                              void* d_out, int out_size) {
    const float *u = nullptr, *W_uh = nullptr, *W_hh = nullptr,
                *W_hy = nullptr, *b_hh = nullptr, *b_hy = nullptr;
    for (int i = 0; i < n_in; i++) {
        const float* p = (const float*)d_in[i];
        switch (in_sizes[i]) {
            case T_STEPS * BATCH * NIN: u    = p; break;  // 16777216
            case NIN * NHID:            W_uh = p; break;  // 65536
            case NHID * NHID:           W_hh = p; break;  // 262144
            case NHID * NOUT:           W_hy = p; break;  // 32768
            case NHID:                  b_hh = p; break;  // 512
            case NOUT:                  b_hy = p; break;  // 64
        }
    }
    if (!u || !W_uh || !W_hh || !W_hy || !b_hh || !b_hy) {
        u    = (const float*)d_in[0];
        W_uh = (const float*)d_in[1];
        W_hh = (const float*)d_in[2];
        W_hy = (const float*)d_in[3];
        b_hh = (const float*)d_in[4];
        b_hy = (const float*)d_in[5];
    }

    float* out    = (float*)d_out;
    float* logits = out;
    const long long full = (long long)BATCH * NOUT + (long long)T_STEPS * BATCH * NHID;
    float* h_all;
    if ((long long)out_size >= full) {
        h_all = out + BATCH * NOUT;
    } else {
        void* sym = nullptr;
        cudaGetSymbolAddress(&sym, g_hall);
        h_all = (float*)sym;
    }

    // protocol-free scan: 64 CTAs, one batch row each
    scan_kernel<<<BATCH, THREADS>>>(u, W_uh, W_hh, b_hh, h_all);

    // logits from h_{T-1}
    const float* h_last = h_all + (size_t)(T_STEPS - 1) * BATCH * NHID;
    logits_kernel<<<BATCH, NOUT>>>(h_last, W_hy, b_hy, logits);
}

// round 15
// speedup vs baseline: 3.0635x; 3.0635x over previous
#include <cuda_runtime.h>
#include <cstdint>
#include <cstddef>

#define T_STEPS 2048
#define BATCH   64
#define NIN     128
#define NHID    512
#define NOUT    64

#define CL      8            // ranks (column slices) per group
#define JT      64           // columns per CTA
#define BG      4            // batch rows per group
#define NGRP    (BATCH/BG)   // 16 groups
#define SGRID   (NGRP*CL)    // 128 CTAs
#define THR     128

// Device-global scratch (load-time allocation)
__device__ float g_hall[(size_t)T_STEPS * BATCH * NHID];   // h_all fallback
__device__ float g_H[2][NGRP][NHID][BG];                   // h exchange [k][b]
__device__ int   g_flag[NGRP][CL];                         // step flags

// ---- L2-coherent access helpers ----
__device__ __forceinline__ float4 ldg_cv4(const float4* p) {
    float4 v;
    asm volatile("ld.global.cv.v4.f32 {%0,%1,%2,%3}, [%4];"
                 : "=f"(v.x), "=f"(v.y), "=f"(v.z), "=f"(v.w) : "l"(p) : "memory");
    return v;
}
__device__ __forceinline__ int ldg_cv_i(const int* p) {
    int v;
    asm volatile("ld.global.cv.s32 %0, [%1];" : "=r"(v) : "l"(p) : "memory");
    return v;
}
__device__ __forceinline__ void stg_cg_v2(float* p, float a, float b) {
    asm volatile("st.global.cg.v2.f32 [%0], {%1,%2};" :: "l"(p), "f"(a), "f"(b) : "memory");
}

// ---- XLA llvm_ir::EmitFastTanh, with_fma = true (VERBATIM from passing R13) ----
__device__ __forceinline__ float tanh_xla(float x) {
    const float kClamp = 7.99881172180175781f;
    float xc = fminf(fmaxf(x, -kClamp), kClamp);
    float x2 = __fmul_rn(xc, xc);
    float p = -2.76076847742355e-16f;                 // alpha_13
    p = fmaf(x2, p,  2.00018790482477e-13f);          // alpha_11
    p = fmaf(x2, p, -8.60467152213735e-11f);          // alpha_9
    p = fmaf(x2, p,  5.12229709037114e-08f);          // alpha_7
    p = fmaf(x2, p,  1.48572235717979e-05f);          // alpha_5
    p = fmaf(x2, p,  6.37261928875436e-04f);          // alpha_3
    p = fmaf(x2, p,  4.89352455891786e-03f);          // alpha_1
    p = __fmul_rn(xc, p);
    float q = 1.19825839466702e-06f;                  // beta_6
    q = fmaf(x2, q,  1.18534705686654e-04f);          // beta_4
    q = fmaf(x2, q,  2.26843463243900e-03f);          // beta_2
    q = fmaf(x2, q,  4.89352518554385e-03f);          // beta_0
    float r = __fdiv_rn(p, q);
    return (fabsf(x) < 0.0004f) ? x : r;
}

// ---------------- Kernel 0: reset exchange state (every replay) ----------------
__global__ void init_kernel() {
    int i = blockIdx.x * blockDim.x + threadIdx.x;
    if (i < 2 * NGRP * NHID * BG) ((float*)g_H)[i] = 0.f;   // BOTH parities
    if (i < NGRP * CL)            ((int*)g_flag)[i] = 0;
}

// ---------------- Kernel 1: recurrent scan, W SMEM-resident, inline u ----------
// 128 CTAs: group gid owns batch rows [4g,4g+4); rank owns cols [64r,64r+64)
// of BOTH W_hh and W_uh, SMEM-resident. Thread (j = tid&63, bp = tid>>6)
// computes rows 2bp, 2bp+1 of column j0+j via the EXACT R13 arithmetic:
//   dot_h = sum_{k=0..511 asc} fmaf(h[k], W_hh[k][j'], .)   (acc from 0)
//   dot_u = sum_{i=0..127 asc} fmaf(u[b][i], W_uh[i][j'], .)(acc from 0)
//   val   = tanh_xla( fadd(dot_h, fadd(dot_u, b_hh[j'])) )
__global__ void __launch_bounds__(THR, 1)
scan_kernel(const float* __restrict__ u,
            const float* __restrict__ W_uh,
            const float* __restrict__ W_hh,
            const float* __restrict__ b_hh,
            float* __restrict__ h_all) {
    extern __shared__ float smem[];
    float* Ws = smem;                    // [512][64] 128 KB  W_hh slice
    float* Wu = Ws + NHID * JT;          // [128][64]  32 KB  W_uh slice
    float* hS = Wu + NIN * JT;           // [512][4]    8 KB  h_t, [k][b]
    float* uL = hS + NHID * BG;          // [4][128]    2 KB  u_t rows

    const int tid  = threadIdx.x;
    const int rank = blockIdx.x & (CL - 1);
    const int gid  = blockIdx.x >> 3;
    const int b0   = gid * BG;
    const int j0   = rank * JT;

    // Resident weight slices (exact copies of input values)
    for (int idx = tid; idx < NHID * JT; idx += THR)
        Ws[idx] = W_hh[(size_t)(idx >> 6) * NHID + j0 + (idx & 63)];
    for (int idx = tid; idx < NIN * JT; idx += THR)
        Wu[idx] = W_uh[(size_t)(idx >> 6) * NHID + j0 + (idx & 63)];
    __syncthreads();

    const int j  = tid & 63;
    const int bp = tid >> 6;             // 0..1 -> local rows 2bp, 2bp+1
    const int b2 = bp * 2;

    const float bh = b_hh[j0 + j];
    const size_t row_off = (size_t)(b0 + b2) * NHID + j0 + j;
    float* const slab0 = &g_H[0][gid][0][0];
    const size_t PSTR  = (size_t)NGRP * NHID * BG;           // parity stride
    float* const pub0  = &g_H[0][gid][j0 + j][b2];

    float badv = 0.f;                    // corruption sentinel accumulator

    for (int t = 0; t < T_STEPS; t++) {
        const int cur = t & 1;
        const int nxt = cur ^ 1;

        // ---- acquire: all 8 slices of h_t published, then acquire fence ----
        if (tid < CL) {
            const int* f = &g_flag[gid][tid];
            while (ldg_cv_i(f) < t) { }
            __threadfence();             // acquire: order flag before data reads
        }
        __syncthreads();

        // ---- copy h_t slab (8 KB, layout [k][b]) L2 -> SMEM, with sentinel ----
        {
            const float4* src = (const float4*)(slab0 + (size_t)cur * PSTR);
            float4* dst = (float4*)hS;
#pragma unroll
            for (int q = 0; q < 4; q++) {
                float4 v = ldg_cv4(src + tid + q * THR);
                dst[tid + q * THR] = v;
                badv = fmaxf(badv, fmaxf(fmaxf(fabsf(v.x), fabsf(v.y)),
                                         fmaxf(fabsf(v.z), fabsf(v.w))));
            }
        }
        // ---- stage u_t rows: uL[b][i] (exact copies) ----
#pragma unroll
        for (int q = 0; q < 4; q++) {
            int i = tid + q * THR;       // 0..511
            uL[i] = u[((size_t)t * BATCH + b0 + (i >> 7)) * NIN + (i & 127)];
        }
        __syncthreads();

        // ---- dot_h: EXACT R13 chains, k = 0..511 ascending, acc from 0 ----
        float aA = 0.f, aB = 0.f;
        {
            const float* wp = Ws + j;
            const float* hp = hS + b2;
#pragma unroll 8
            for (int k = 0; k < NHID; k++) {
                float2 h2 = *(const float2*)(hp + k * BG);   // rows b2, b2+1
                float  w  = wp[k * JT];
                aA = fmaf(h2.x, w, aA);
                aB = fmaf(h2.y, w, aB);
            }
        }
        // ---- dot_u: EXACT R13 chains, i = 0..127 ascending, acc from 0 ----
        float uA = 0.f, uB = 0.f;
        {
            const float* wq  = Wu + j;
            const float* upA = uL + b2 * NIN;
            const float* upB = upA + NIN;
#pragma unroll 8
            for (int i = 0; i < NIN; i++) {
                float w = wq[i * JT];
                uA = fmaf(upA[i], w, uA);
                uB = fmaf(upB[i], w, uB);
            }
        }

        // ---- reference combine: tanh( dot_h + (dot_u + bias) ) ----
        float vA = tanh_xla(__fadd_rn(aA, __fadd_rn(uA, bh)));
        float vB = tanh_xla(__fadd_rn(aB, __fadd_rn(uB, bh)));

        // stream h_{t+1} to output tensor
        float* ho = h_all + (size_t)t * (BATCH * NHID) + row_off;
        ho[0]    = vA;
        ho[NHID] = vB;

        // ---- publish + release ----
        stg_cg_v2(pub0 + (size_t)nxt * PSTR, vA, vB);
        __threadfence();                 // each thread: its store visible
        __syncthreads();
        if (tid == 0) {
            __threadfence();             // release fence before flag
            atomicExch(&g_flag[gid][rank], t + 1);
        }
    }

    // corruption sentinel: tanh outputs satisfy |v| < 1; anything larger means
    // the exchange delivered garbage -> make the failure unmistakable.
    if (badv > 1.0001f)
        h_all[1] = 1.0e30f;
}

// ---------------- Kernel 2: logits (VERBATIM from passing R13) ----------------
__global__ __launch_bounds__(64) void logits_kernel(const float* __restrict__ h_last,
                                                    const float* __restrict__ W_hy,
                                                    const float* __restrict__ b_hy,
                                                    float* __restrict__ out) {
    __shared__ float hrow[NHID];
    const int bi = blockIdx.x;
    for (int k = threadIdx.x; k < NHID; k += blockDim.x)
        hrow[k] = h_last[(size_t)bi * NHID + k];
    __syncthreads();
    const int o = threadIdx.x;
    float acc = 0.f;
    for (int k = 0; k < NHID; k++)
        acc = fmaf(hrow[k], W_hy[(size_t)k * NOUT + o], acc);
    out[(size_t)bi * NOUT + o] = __fadd_rn(acc, b_hy[o]);
}

// ---------------- launch ----------------
extern "C" void kernel_launch(void* const* d_in, const int* in_sizes, int n_in,
                              void* d_out, int out_size) {
    const float *u = nullptr, *W_uh = nullptr, *W_hh = nullptr,
                *W_hy = nullptr, *b_hh = nullptr, *b_hy = nullptr;
    for (int i = 0; i < n_in; i++) {
        const float* p = (const float*)d_in[i];
        switch (in_sizes[i]) {
            case T_STEPS * BATCH * NIN: u    = p; break;  // 16777216
            case NIN * NHID:            W_uh = p; break;  // 65536
            case NHID * NHID:           W_hh = p; break;  // 262144
            case NHID * NOUT:           W_hy = p; break;  // 32768
            case NHID:                  b_hh = p; break;  // 512
            case NOUT:                  b_hy = p; break;  // 64
        }
    }
    if (!u || !W_uh || !W_hh || !W_hy || !b_hh || !b_hy) {
        u    = (const float*)d_in[0];
        W_uh = (const float*)d_in[1];
        W_hh = (const float*)d_in[2];
        W_hy = (const float*)d_in[3];
        b_hh = (const float*)d_in[4];
        b_hy = (const float*)d_in[5];
    }

    float* out    = (float*)d_out;
    float* logits = out;
    const long long full = (long long)BATCH * NOUT + (long long)T_STEPS * BATCH * NHID;
    float* h_all;
    if ((long long)out_size >= full) {
        h_all = out + BATCH * NOUT;
    } else {
        void* sym = nullptr;
        cudaGetSymbolAddress(&sym, g_hall);
        h_all = (float*)sym;
    }

    // 0) reset exchange buffers + flags (graph-replay safe)
    init_kernel<<<(2 * NGRP * NHID * BG + 255) / 256, 256>>>();

    // 1) recurrent scan: 128 CTAs, W slices SMEM-resident, hardened exchange
    {
        size_t shmem = (size_t)(NHID * JT + NIN * JT + NHID * BG + BG * NIN)
                       * sizeof(float);                   // 174080 B
        cudaFuncSetAttribute(scan_kernel,
                             cudaFuncAttributeMaxDynamicSharedMemorySize, (int)shmem);
        scan_kernel<<<SGRID, THR, shmem>>>(u, W_uh, W_hh, b_hh, h_all);
    }

    // 2) logits from h_{T-1}
    {
        const float* h_last = h_all + (size_t)(T_STEPS - 1) * BATCH * NHID;
        logits_kernel<<<BATCH, NOUT>>>(h_last, W_hy, b_hy, logits);
    }
}